// round 5
// baseline (speedup 1.0000x reference)
#include <cuda_runtime.h>
#include <cstdint>

// ---------------------------------------------------------------------------
// EmbeddingLoss: B=4, E=16, S=96, K=32 clusters.
//   k_prep : BCE partials + per-label u8 counts + packed seg[] (255 = masked out)
//   k_bins : per-(b,e,chunk) segmented sum & sumsq, thread-private smem bins,
//            4-deep register prefetch ring (guaranteed LDG MLP, no spills)
//   k_final: deterministic reduction + centers/internal/hinge/reg + BCE
// No device allocation; scratch in __device__ globals. Fixed-order reductions
// (no float atomics) -> bit-deterministic across graph replays.
// ---------------------------------------------------------------------------

constexpr int B_   = 4;
constexpr int E_   = 16;
constexpr int N_   = 96 * 96 * 96;   // 884736 voxels per batch
constexpr int N4_  = N_ / 4;         // 221184 float4 groups
constexpr int KC   = 32;

constexpr int CH0   = 288;           // prep chunks per batch
constexpr int C4_0  = N4_ / CH0;     // 768
constexpr int T0    = 256;
constexpr int IT0   = C4_0 / T0;     // 3

constexpr int CHA   = 54;            // binning chunks per (b,e)
constexpr int C4_A  = N4_ / CHA;     // 4096
constexpr int TA    = 128;
constexpr int ITA   = C4_A / TA;     // 32
constexpr int GRIDA = CHA * 64;      // 3456 blocks total (split into 2 launches)

// scratch (fully written each launch before read -> no zero-init needed)
__device__ unsigned char g_seg[B_ * N_];                 // 3.5 MB, L2-resident
__device__ float2        g_pSum[64 * CHA * KC];          // [be][ch][k] (sum, sumsq)
__device__ float         g_pCnt[B_ * CH0 * KC];          // [b][ch0][k]
__device__ float         g_pBce[B_ * CH0];

// ---------------------------------------------------------------------------
// Kernel 0: prep. grid = B*CH0 = 1152 blocks, 256 threads, 3 iters/thread.
// ---------------------------------------------------------------------------
__global__ __launch_bounds__(T0) void k_prep(const float* __restrict__ masks,
                                             const int*   __restrict__ lbl,
                                             const float* __restrict__ tmask)
{
    __shared__ unsigned char sCnt[T0 * 33];   // u8 per-thread bins (max 12/bin)
    __shared__ float sRedC[8 * 32];
    __shared__ float sRedB[8];

    const int tid = threadIdx.x;
    const int bid = blockIdx.x;
    const int b   = bid / CH0;
    const int ch  = bid - b * CH0;
    const long base4 = (long)b * N4_ + (long)ch * C4_0;

    unsigned char* mybin = &sCnt[tid * 33];
#pragma unroll
    for (int k = 0; k < KC; k++) mybin[k] = 0;

    const int4*   lv = (const int4*)lbl     + base4;
    const float4* tv = (const float4*)tmask + base4;
    const float4* xv = (const float4*)masks + base4;
    uchar4*       sv = (uchar4*)g_seg + base4;

    float bce = 0.f;
#pragma unroll
    for (int it = 0; it < IT0; it++) {
        const int i = tid + it * T0;
        int4   L = __ldcs(&lv[i]);
        float4 T = __ldcs(&tv[i]);
        float4 X = __ldcs(&xv[i]);
        uchar4 s;
#define PREP1(comp)                                                            \
        {                                                                      \
            bool m = (T.comp != 0.f) && ((unsigned)L.comp < 32u);              \
            s.comp = m ? (unsigned char)L.comp : (unsigned char)255;           \
            if (m) mybin[L.comp] = mybin[L.comp] + 1;                          \
            float a = fabsf(X.comp);                                           \
            bce += fmaxf(X.comp, 0.f) - X.comp * T.comp                        \
                 + __logf(1.f + __expf(-a));                                   \
        }
        PREP1(x) PREP1(y) PREP1(z) PREP1(w)
#undef PREP1
        sv[i] = s;
    }
    __syncthreads();

    const int lane = tid & 31, w = tid >> 5;   // 8 warps
    float acc = 0.f;
#pragma unroll 8
    for (int t = 0; t < 32; t++) acc += (float)sCnt[(w * 32 + t) * 33 + lane];
    sRedC[w * 32 + lane] = acc;

    float bb = bce;
#pragma unroll
    for (int o = 16; o; o >>= 1) bb += __shfl_xor_sync(0xffffffffu, bb, o);
    if (lane == 0) sRedB[w] = bb;
    __syncthreads();

    if (w == 0) {
        float tot = 0.f;
#pragma unroll
        for (int q = 0; q < 8; q++) tot += sRedC[q * 32 + lane];
        g_pCnt[(b * CH0 + ch) * KC + lane] = tot;
        if (lane == 0) {
            float bt = 0.f;
#pragma unroll
            for (int q = 0; q < 8; q++) bt += sRedB[q];
            g_pBce[bid] = bt;
        }
    }
}

// ---------------------------------------------------------------------------
// Kernel A: segmented sum/sumsq. 128 threads. 64 consecutive blocks share one
// seg chunk (L2 reuse of the 16x-read seg). Thread-private interleaved bins
// bins[k*128+tid]: bank = (tid*2) mod 32 -> conflict-free LDS.64/STS.64 RMW.
// 4-deep register prefetch ring keeps 4 iterations of LDG.128 in flight.
// ---------------------------------------------------------------------------
__global__ __launch_bounds__(TA, 7) void k_bins(const float* __restrict__ emb,
                                                int bid_base)
{
    __shared__ float2 bins[KC * TA];  // exactly 32 KB

    const int tid = threadIdx.x;
    const int bid = blockIdx.x + bid_base;
    const int ch  = bid >> 6;          // 0..CHA-1 (same for 64 consecutive bids)
    const int be  = bid & 63;          // b*16 + e
    const int b   = be >> 4;

#pragma unroll
    for (int k = 0; k < KC; k++) bins[k * TA + tid] = make_float2(0.f, 0.f);

    const float4* evp = (const float4*)emb   + (long)be * N4_ + (long)ch * C4_A + tid;
    const uchar4* svp = (const uchar4*)g_seg + (long)b  * N4_ + (long)ch * C4_A + tid;

    float4 vb[4];
    uchar4 sb[4];
#pragma unroll
    for (int p = 0; p < 4; p++) {
        vb[p] = __ldcs(&evp[p * TA]);
        sb[p] = __ldg(&svp[p * TA]);
    }

#pragma unroll 4
    for (int it = 0; it < ITA; it++) {
        float4 v = vb[it & 3];
        uchar4 s = sb[it & 3];
        if (it + 4 < ITA) {                       // prefetch 4 ahead
            vb[it & 3] = __ldcs(&evp[(it + 4) * TA]);
            sb[it & 3] = __ldg(&svp[(it + 4) * TA]);
        }
#define ACC1(sc, vc)                                                   \
        if (s.sc != 255) {                                             \
            float2 a = bins[(int)s.sc * TA + tid];                     \
            a.x += v.vc; a.y += v.vc * v.vc;                           \
            bins[(int)s.sc * TA + tid] = a;                            \
        }
        ACC1(x, x) ACC1(y, y) ACC1(z, z) ACC1(w, w)
#undef ACC1
    }
    __syncthreads();

    const int lane = tid & 31, w = tid >> 5;
    // warp w sums bin k=lane over thread columns [w*32, w*32+32)
    float2 acc = make_float2(0.f, 0.f);
#pragma unroll 8
    for (int t = 0; t < 32; t++) {
        float2 x = bins[lane * TA + (w * 32 + t)];
        acc.x += x.x; acc.y += x.y;
    }
    __syncthreads();                   // all reads done -> safe to reuse bins
    bins[w * 32 + lane] = acc;         // slots 0..127 (row k=0, already consumed)
    __syncthreads();

    if (w == 0) {
        float2 tot = make_float2(0.f, 0.f);
#pragma unroll
        for (int q = 0; q < 4; q++) {
            float2 x = bins[q * 32 + lane];
            tot.x += x.x; tot.y += x.y;
        }
        g_pSum[(long)(be * CHA + ch) * KC + lane] = tot;
    }
}

// ---------------------------------------------------------------------------
// Kernel B: finalize. 1 block, 512 threads.
// ---------------------------------------------------------------------------
__global__ __launch_bounds__(512) void k_final(float* __restrict__ out)
{
    __shared__ float2 sSum[B_ * E_ * KC];     // [b][e][k]  16 KB
    __shared__ float  sCntP[B_ * 4 * KC];     // 2 KB
    __shared__ float  sCent[B_][KC][E_];      // 8 KB
    __shared__ float  sRes[B_][3];
    __shared__ float  sBce;

    const int tid  = threadIdx.x;
    const int b    = tid >> 7;
    const int sub  = tid & 127;
    const int k    = sub & 31;
    const int part = sub >> 5;                // 0..3

    // reduce channel sums over chunks (each (b,e,k) owned by one thread)
#pragma unroll
    for (int i = 0; i < 4; i++) {
        const int e = part * 4 + i;
        float2 acc = make_float2(0.f, 0.f);
        const float2* p = &g_pSum[(long)((b * E_ + e) * CHA) * KC + k];
#pragma unroll 9
        for (int ch = 0; ch < CHA; ch++) {
            float2 x = p[(long)ch * KC];
            acc.x += x.x; acc.y += x.y;
        }
        sSum[(b * E_ + e) * KC + k] = acc;
    }
    // reduce counts: part covers CH0/4 = 72 chunks
    {
        float c = 0.f;
#pragma unroll 8
        for (int c0 = part * (CH0 / 4); c0 < (part + 1) * (CH0 / 4); c0++)
            c += g_pCnt[(b * CH0 + c0) * KC + k];
        sCntP[(b * 4 + part) * KC + k] = c;
    }
    // reduce BCE (warp 0): B*CH0 = 1152 partials
    if (tid < 32) {
        float a = 0.f;
        for (int q = tid; q < B_ * CH0; q += 32) a += g_pBce[q];
#pragma unroll
        for (int o = 16; o; o >>= 1) a += __shfl_xor_sync(0xffffffffu, a, o);
        if (tid == 0) sBce = a;
    }
    __syncthreads();

    if (tid < 128) {
        const int bb   = tid >> 5;
        const int lane = tid & 31;
        float cnt = sCntP[(bb * 4 + 0) * KC + lane] + sCntP[(bb * 4 + 1) * KC + lane]
                  + sCntP[(bb * 4 + 2) * KC + lane] + sCntP[(bb * 4 + 3) * KC + lane];
        float safe = fmaxf(cnt, 1.f);
        float center[E_];
        float sq = 0.f, cs = 0.f;
#pragma unroll
        for (int e = 0; e < E_; e++) {
            float2 s = sSum[(bb * E_ + e) * KC + lane];
            float c = s.x / safe;
            center[e] = c;
            cs += c * c;
            sq += s.y;
        }
        bool fg = (cnt > 0.f) && (lane > 0);
        unsigned fgm = __ballot_sync(0xffffffffu, fg);
        float C = (float)__popc(fgm);
#pragma unroll
        for (int e = 0; e < E_; e++) sCent[bb][lane][e] = center[e];
        __syncwarp();

        float internal_j = sq / safe - cs;
        float vi = fg ? internal_j : 0.f;
        float vr = fg ? sqrtf(cs) : 0.f;
        float hs = 0.f;
        for (int j = 0; j < KC; j++) {
            if ((fgm >> j) & 1u) {
                float d2 = 0.f;
#pragma unroll
                for (int e = 0; e < E_; e++) {
                    float d = center[e] - sCent[bb][j][e];
                    d2 += d * d;
                }
                if (fg && j != lane) {
                    float d = sqrtf(d2);
                    float h = fmaxf(2.f * 1.5f - d, 0.f);
                    hs += h * h;
                }
            }
        }
#pragma unroll
        for (int o = 16; o; o >>= 1) {
            vi += __shfl_xor_sync(0xffffffffu, vi, o);
            vr += __shfl_xor_sync(0xffffffffu, vr, o);
            hs += __shfl_xor_sync(0xffffffffu, hs, o);
        }
        if (lane == 0) {
            float Cs = fmaxf(C, 1.f);
            sRes[bb][0] = (C >= 1.f) ? vi / Cs : 0.f;                           // internal
            sRes[bb][1] = (C >= 2.f) ? hs / fmaxf(C * (C - 1.f), 1.f) : 0.f;     // external
            sRes[bb][2] = (C >= 1.f) ? vr / Cs : 0.f;                           // reg
        }
    }
    __syncthreads();

    if (tid == 0) {
        float mi = 0.f, me = 0.f, mr = 0.f;
#pragma unroll
        for (int q = 0; q < B_; q++) { mi += sRes[q][0]; me += sRes[q][1]; mr += sRes[q][2]; }
        mi *= 0.25f; me *= 0.25f; mr *= 0.25f;
        float bce = sBce / (float)((long)B_ * N_);
        // total = ALPHA*internal + BETA*external + GAMMA + reg + bce
        out[0] = 1.0f * mi + 1.0f * me + 0.001f + mr + bce;
    }
}

// ---------------------------------------------------------------------------
extern "C" void kernel_launch(void* const* d_in, const int* in_sizes, int n_in,
                              void* d_out, int out_size)
{
    (void)in_sizes; (void)n_in; (void)out_size;
    const float* emb   = (const float*)d_in[0];  // [4,16,96^3] f32
    const float* masks = (const float*)d_in[1];  // [4,1,96^3]  f32 logits
    const int*   lbl   = (const int*)d_in[2];    // [4,1,96^3]  int32 labels
    const float* tmask = (const float*)d_in[3];  // [4,1,96^3]  f32 0/1
    float* out = (float*)d_out;

    k_prep <<<B_ * CH0, T0>>>(masks, lbl, tmask);
    // split into two launches so the ncu capture window (-s 5 -c 1) lands on k_bins
    k_bins <<<GRIDA / 2, TA>>>(emb, 0);
    k_bins <<<GRIDA / 2, TA>>>(emb, GRIDA / 2);
    k_final<<<1, 512>>>(out);
}

// round 7
// speedup vs baseline: 1.1387x; 1.1387x over previous
#include <cuda_runtime.h>
#include <cstdint>

// ---------------------------------------------------------------------------
// EmbeddingLoss: B=4, E=16, S=96, K=32 clusters.
//   k_prep : BCE partials + per-label u8 counts + packed seg[] (255 = masked)
//   k_bins : segmented sum/sumsq, thread-private smem bins, dup-merged batched
//            RMW (4 LDS then 4 STS), 4-deep LDG prefetch ring, single wave
//   k_mid  : parallel reduction of chunk partials (sums / counts / bce)
//   k_final: tiny: centers/internal/hinge/reg + BCE -> scalar
// No device allocation. Fixed-order reductions -> bit-deterministic.
// ---------------------------------------------------------------------------

constexpr int B_   = 4;
constexpr int E_   = 16;
constexpr int N_   = 96 * 96 * 96;   // 884736 voxels per batch
constexpr int N4_  = N_ / 4;         // 221184 float4 groups
constexpr int KC   = 32;

constexpr int CH0   = 288;           // prep chunks per batch
constexpr int C4_0  = N4_ / CH0;     // 768
constexpr int T0    = 256;
constexpr int IT0   = C4_0 / T0;     // 3

constexpr int CHA   = 16;            // binning chunks per (b,e)
constexpr int C4_A  = N4_ / CHA;     // 13824
constexpr int TA    = 128;
constexpr int ITA   = C4_A / TA;     // 108
constexpr int GRIDA = CHA * 64;      // 1024 blocks = one wave @ occ 7

// scratch (fully written each launch before read -> no zero-init needed)
__device__ unsigned char g_seg[B_ * N_];                 // 3.5 MB, L2-resident
__device__ float2        g_pSum[64 * CHA * KC];          // [be][ch][k]
__device__ float         g_pCnt[B_ * CH0 * KC];          // [b][ch0][k]
__device__ float         g_pBce[B_ * CH0];
__device__ float2        g_sSum[64 * KC];                // reduced [be][k]
__device__ float         g_sCnt[B_ * KC];                // reduced [b][k]
__device__ float         g_sBce;

// ---------------------------------------------------------------------------
// Kernel 0: prep. grid = B*CH0 = 1152 blocks, 256 threads, 3 iters/thread.
// ---------------------------------------------------------------------------
__global__ __launch_bounds__(T0) void k_prep(const float* __restrict__ masks,
                                             const int*   __restrict__ lbl,
                                             const float* __restrict__ tmask)
{
    __shared__ unsigned char sCnt[T0 * 33];   // u8 per-thread bins (max 12/bin)
    __shared__ float sRedC[8 * 32];
    __shared__ float sRedB[8];

    const int tid = threadIdx.x;
    const int bid = blockIdx.x;
    const int b   = bid / CH0;
    const int ch  = bid - b * CH0;
    const long base4 = (long)b * N4_ + (long)ch * C4_0;

    unsigned char* mybin = &sCnt[tid * 33];
#pragma unroll
    for (int k = 0; k < KC; k++) mybin[k] = 0;

    const int4*   lv = (const int4*)lbl     + base4;
    const float4* tv = (const float4*)tmask + base4;
    const float4* xv = (const float4*)masks + base4;
    uchar4*       sv = (uchar4*)g_seg + base4;

    float bce = 0.f;
#pragma unroll
    for (int it = 0; it < IT0; it++) {
        const int i = tid + it * T0;
        int4   L = __ldcs(&lv[i]);
        float4 T = __ldcs(&tv[i]);
        float4 X = __ldcs(&xv[i]);
        uchar4 s;
#define PREP1(comp)                                                            \
        {                                                                      \
            bool m = (T.comp != 0.f) && ((unsigned)L.comp < 32u);              \
            s.comp = m ? (unsigned char)L.comp : (unsigned char)255;           \
            if (m) mybin[L.comp] = mybin[L.comp] + 1;                          \
            float a = fabsf(X.comp);                                           \
            bce += fmaxf(X.comp, 0.f) - X.comp * T.comp                        \
                 + __logf(1.f + __expf(-a));                                   \
        }
        PREP1(x) PREP1(y) PREP1(z) PREP1(w)
#undef PREP1
        sv[i] = s;
    }
    __syncthreads();

    const int lane = tid & 31, w = tid >> 5;   // 8 warps
    float acc = 0.f;
#pragma unroll 8
    for (int t = 0; t < 32; t++) acc += (float)sCnt[(w * 32 + t) * 33 + lane];
    sRedC[w * 32 + lane] = acc;

    float bb = bce;
#pragma unroll
    for (int o = 16; o; o >>= 1) bb += __shfl_xor_sync(0xffffffffu, bb, o);
    if (lane == 0) sRedB[w] = bb;
    __syncthreads();

    if (w == 0) {
        float tot = 0.f;
#pragma unroll
        for (int q = 0; q < 8; q++) tot += sRedC[q * 32 + lane];
        g_pCnt[(b * CH0 + ch) * KC + lane] = tot;
        if (lane == 0) {
            float bt = 0.f;
#pragma unroll
            for (int q = 0; q < 8; q++) bt += sRedB[q];
            g_pBce[bid] = bt;
        }
    }
}

// ---------------------------------------------------------------------------
// Kernel A: segmented sum/sumsq. grid = 1024 (one wave @ occ 7), 128 threads.
// 64 consecutive blocks share one seg chunk (L2 reuse). Interleaved bins
// bins[k*128+tid] -> conflict-free LDS.64/STS.64. Duplicate labels among the
// 4 components are merged in registers so the 4 loads can issue before any
// store (no serial alias chain). 4-deep LDG prefetch ring.
// ---------------------------------------------------------------------------
__global__ __launch_bounds__(TA, 7) void k_bins(const float* __restrict__ emb)
{
    __shared__ float2 bins[KC * TA];  // exactly 32 KB

    const int tid = threadIdx.x;
    const int bid = blockIdx.x;
    const int ch  = bid >> 6;          // 0..CHA-1 (same for 64 consecutive bids)
    const int be  = bid & 63;          // b*16 + e
    const int b   = be >> 4;

#pragma unroll
    for (int k = 0; k < KC; k++) bins[k * TA + tid] = make_float2(0.f, 0.f);

    const float4* evp = (const float4*)emb   + (long)be * N4_ + (long)ch * C4_A + tid;
    const uchar4* svp = (const uchar4*)g_seg + (long)b  * N4_ + (long)ch * C4_A + tid;

    float4 vb[4];
    uchar4 sb[4];
#pragma unroll
    for (int p = 0; p < 4; p++) {
        vb[p] = __ldcs(&evp[p * TA]);
        sb[p] = __ldg(&svp[p * TA]);
    }

#pragma unroll 4
    for (int it = 0; it < ITA; it++) {
        float4 v = vb[it & 3];
        uchar4 s = sb[it & 3];
        if (it + 4 < ITA) {                       // prefetch 4 ahead
            vb[it & 3] = __ldcs(&evp[(it + 4) * TA]);
            sb[it & 3] = __ldg(&svp[(it + 4) * TA]);
        }
        // contributions, merging duplicates into the earliest equal slot
        float cx = v.x, cy = v.y, cz = v.z, cw = v.w;
        float qx = v.x * v.x, qy = v.y * v.y, qz = v.z * v.z, qw = v.w * v.w;
        const bool eyx = (s.y == s.x);
        const bool ezx = (s.z == s.x), ezy = (s.z == s.y);
        const bool ewx = (s.w == s.x), ewy = (s.w == s.y), ewz = (s.w == s.z);
        if (eyx) { cx += cy; qx += qy; }
        if (ezx) { cx += cz; qx += qz; } else if (ezy) { cy += cz; qy += qz; }
        if (ewx) { cx += cw; qx += qw; }
        else if (ewy) { cy += cw; qy += qw; }
        else if (ewz) { cz += cw; qz += qw; }
        const bool lx = (s.x != 255);
        const bool ly = (s.y != 255) && !eyx;
        const bool lz = (s.z != 255) && !ezx && !ezy;
        const bool lw = (s.w != 255) && !ewx && !ewy && !ewz;

        float2* px = &bins[(s.x & 31) * TA + tid];
        float2* py = &bins[(s.y & 31) * TA + tid];
        float2* pz = &bins[(s.z & 31) * TA + tid];
        float2* pw = &bins[(s.w & 31) * TA + tid];
        float2 ax = *px;                 // 4 independent LDS.64, overlapped
        float2 ay = *py;
        float2 az = *pz;
        float2 aw = *pw;
        ax.x += cx; ax.y += qx;
        ay.x += cy; ay.y += qy;
        az.x += cz; az.y += qz;
        aw.x += cw; aw.y += qw;
        if (lx) *px = ax;                // dead/merged slots not stored
        if (ly) *py = ay;
        if (lz) *pz = az;
        if (lw) *pw = aw;
    }
    __syncthreads();

    const int lane = tid & 31, w = tid >> 5;
    // warp w sums bin k=lane over a +lane-swizzled column permutation:
    // bank = ((c+lane)*2) mod 32 -> conflict-free (was 16-way conflicted).
    float2 acc = make_float2(0.f, 0.f);
#pragma unroll 8
    for (int t = 0; t < 32; t++) {
        float2 x = bins[lane * TA + ((w * 32 + t + lane) & (TA - 1))];
        acc.x += x.x; acc.y += x.y;
    }
    __syncthreads();                   // all reads done -> safe to reuse bins
    bins[w * 32 + lane] = acc;
    __syncthreads();

    if (w == 0) {
        float2 tot = make_float2(0.f, 0.f);
#pragma unroll
        for (int q = 0; q < 4; q++) {
            float2 x = bins[q * 32 + lane];
            tot.x += x.x; tot.y += x.y;
        }
        g_pSum[(long)(be * CHA + ch) * KC + lane] = tot;
    }
}

// ---------------------------------------------------------------------------
// Kernel M: parallel partial reduction. grid = 69 blocks, 128 threads.
//   blocks 0..63 : g_pSum chunks -> g_sSum[be][k]
//   blocks 64..67: g_pCnt chunks -> g_sCnt[b][k]
//   block  68    : g_pBce        -> g_sBce
// ---------------------------------------------------------------------------
__global__ __launch_bounds__(128) void k_mid()
{
    __shared__ float2 sS[128];
    const int tid = threadIdx.x, lane = tid & 31, w = tid >> 5;
    const int bid = blockIdx.x;

    if (bid < 64) {
        float2 acc = make_float2(0.f, 0.f);
        const float2* p = &g_pSum[(long)(bid * CHA) * KC + lane];
#pragma unroll
        for (int c = w; c < CHA; c += 4) {
            float2 x = p[(long)c * KC];
            acc.x += x.x; acc.y += x.y;
        }
        sS[tid] = acc;
        __syncthreads();
        if (w == 0) {
            float2 t = make_float2(0.f, 0.f);
#pragma unroll
            for (int q = 0; q < 4; q++) {
                float2 x = sS[q * 32 + lane];
                t.x += x.x; t.y += x.y;
            }
            g_sSum[bid * KC + lane] = t;
        }
    } else if (bid < 68) {
        const int b = bid - 64;
        float c = 0.f;
        for (int c0 = w; c0 < CH0; c0 += 4)
            c += g_pCnt[(b * CH0 + c0) * KC + lane];
        sS[tid].x = c;
        __syncthreads();
        if (w == 0) {
            float t = 0.f;
#pragma unroll
            for (int q = 0; q < 4; q++) t += sS[q * 32 + lane].x;
            g_sCnt[b * KC + lane] = t;
        }
    } else {
        float a = 0.f;
        for (int q = tid; q < B_ * CH0; q += 128) a += g_pBce[q];
        sS[tid].x = a;
        __syncthreads();
        if (tid < 32) {
            float t = 0.f;
#pragma unroll
            for (int q = 0; q < 4; q++) t += sS[q * 32 + tid].x;
#pragma unroll
            for (int o = 16; o; o >>= 1) t += __shfl_xor_sync(0xffffffffu, t, o);
            if (tid == 0) g_sBce = t;
        }
    }
}

// ---------------------------------------------------------------------------
// Kernel B: finalize. 1 block, 128 threads (warp = batch, lane = cluster).
// ---------------------------------------------------------------------------
__global__ __launch_bounds__(128) void k_final(float* __restrict__ out)
{
    __shared__ float sCent[B_][KC][E_ + 1];   // pad -> conflict-free
    __shared__ float sRes[B_][3];

    const int tid  = threadIdx.x;
    const int bb   = tid >> 5;
    const int lane = tid & 31;

    float cnt  = g_sCnt[bb * KC + lane];
    float safe = fmaxf(cnt, 1.f);
    float center[E_];
    float sq = 0.f, cs = 0.f;
#pragma unroll
    for (int e = 0; e < E_; e++) {
        float2 s = g_sSum[(bb * E_ + e) * KC + lane];
        float c = s.x / safe;
        center[e] = c;
        cs += c * c;
        sq += s.y;
        sCent[bb][lane][e] = c;
    }
    bool fg = (cnt > 0.f) && (lane > 0);
    unsigned fgm = __ballot_sync(0xffffffffu, fg);
    float C = (float)__popc(fgm);
    __syncwarp();

    float internal_j = sq / safe - cs;
    float vi = fg ? internal_j : 0.f;
    float vr = fg ? sqrtf(cs) : 0.f;
    float hs = 0.f;
    for (int j = 0; j < KC; j++) {
        if ((fgm >> j) & 1u) {
            float d2 = 0.f;
#pragma unroll
            for (int e = 0; e < E_; e++) {
                float d = center[e] - sCent[bb][j][e];
                d2 += d * d;
            }
            if (fg && j != lane) {
                float d = sqrtf(d2);
                float h = fmaxf(2.f * 1.5f - d, 0.f);
                hs += h * h;
            }
        }
    }
#pragma unroll
    for (int o = 16; o; o >>= 1) {
        vi += __shfl_xor_sync(0xffffffffu, vi, o);
        vr += __shfl_xor_sync(0xffffffffu, vr, o);
        hs += __shfl_xor_sync(0xffffffffu, hs, o);
    }
    if (lane == 0) {
        float Cs = fmaxf(C, 1.f);
        sRes[bb][0] = (C >= 1.f) ? vi / Cs : 0.f;                          // internal
        sRes[bb][1] = (C >= 2.f) ? hs / fmaxf(C * (C - 1.f), 1.f) : 0.f;    // external
        sRes[bb][2] = (C >= 1.f) ? vr / Cs : 0.f;                          // reg
    }
    __syncthreads();

    if (tid == 0) {
        float mi = 0.f, me = 0.f, mr = 0.f;
#pragma unroll
        for (int q = 0; q < B_; q++) { mi += sRes[q][0]; me += sRes[q][1]; mr += sRes[q][2]; }
        mi *= 0.25f; me *= 0.25f; mr *= 0.25f;
        float bce = g_sBce / (float)((long)B_ * N_);
        // total = ALPHA*internal + BETA*external + GAMMA + reg + bce
        out[0] = 1.0f * mi + 1.0f * me + 0.001f + mr + bce;
    }
}

// ---------------------------------------------------------------------------
extern "C" void kernel_launch(void* const* d_in, const int* in_sizes, int n_in,
                              void* d_out, int out_size)
{
    (void)in_sizes; (void)n_in; (void)out_size;
    const float* emb   = (const float*)d_in[0];  // [4,16,96^3] f32
    const float* masks = (const float*)d_in[1];  // [4,1,96^3]  f32 logits
    const int*   lbl   = (const int*)d_in[2];    // [4,1,96^3]  int32 labels
    const float* tmask = (const float*)d_in[3];  // [4,1,96^3]  f32 0/1
    float* out = (float*)d_out;

    k_prep <<<B_ * CH0, T0>>>(masks, lbl, tmask);
    k_bins <<<GRIDA, TA>>>(emb);
    k_mid  <<<69, 128>>>();
    k_final<<<1, 128>>>(out);
}

// round 8
// speedup vs baseline: 1.2355x; 1.0849x over previous
#include <cuda_runtime.h>
#include <cstdint>

// ---------------------------------------------------------------------------
// EmbeddingLoss, single persistent kernel with software grid barriers.
//   P1: prep  (seg u8, per-block counts, bce partials)
//   P2: bins  (segmented sum/sumsq, thread-private smem bins, ring prefetch)
//   P3: distributed partial reduction
//   P4: block 0 finalize -> scalar
// Barriers use integer atomics only; all FP reductions fixed-order.
// grid=768 blocks x 96 threads, 25.6KB smem -> all blocks resident (occ>=7).
// ---------------------------------------------------------------------------

constexpr int B_   = 4;
constexpr int E_   = 16;
constexpr int N_   = 96 * 96 * 96;   // 884736 voxels per batch
constexpr int N4_  = N_ / 4;         // 221184 float4 groups per batch
constexpr int KC   = 32;
constexpr int T_   = 96;             // threads per block (3 warps)
constexpr int GRID = 768;

constexpr int PV   = (B_ * N4_) / GRID;  // 1152 float4 per prep slice
constexpr int PIT  = PV / T_;            // 12 iters
constexpr int PB   = GRID / B_;          // 192 prep blocks per batch

constexpr int CHA  = 12;                 // bins chunks per (b,e)
constexpr int C4A  = N4_ / CHA;          // 18432 float4 per bins unit
constexpr int BIT  = C4A / T_;           // 192 iters

__device__ unsigned char g_seg[(long)B_ * N_];   // 3.5 MB
__device__ float2        g_pSum[64 * CHA * KC];  // [be][ch][k]
__device__ float         g_pCnt[GRID * KC];      // [prep-block][k]
__device__ float         g_pBce[GRID];
__device__ float2        g_sSum[64 * KC];
__device__ float         g_sCnt[B_ * KC];
__device__ float         g_sBce;

__device__ int          g_barc = 0;
__device__ volatile int g_barg = 0;

__device__ __forceinline__ void grid_sync()
{
    __syncthreads();
    if (threadIdx.x == 0) {
        __threadfence();
        int gen = g_barg;
        if (atomicAdd(&g_barc, 1) == GRID - 1) {
            g_barc = 0;
            __threadfence();
            g_barg = gen + 1;
        } else {
            while (g_barg == gen) { __nanosleep(64); }
            __threadfence();
        }
    }
    __syncthreads();
}

__global__ __launch_bounds__(T_, 7) void k_all(const float* __restrict__ emb,
                                               const float* __restrict__ masks,
                                               const int*   __restrict__ lbl,
                                               const float* __restrict__ tmask,
                                               float*       __restrict__ out)
{
    __shared__ __align__(16) unsigned char sraw[25600];   // unioned per phase

    const int tid  = threadIdx.x;
    const int bid  = blockIdx.x;
    const int lane = tid & 31;
    const int w    = tid >> 5;     // 0..2

    // ======================= P1: prep =======================
    {
        unsigned char* cnt8 = sraw;                       // 96*33 = 3168 B
        float* redC = (float*)(sraw + 3168);              // 3*32 floats
        float* redB = (float*)(sraw + 3168 + 3 * 32 * 4); // 3 floats

        unsigned char* mybin = cnt8 + tid * 33;
#pragma unroll
        for (int k = 0; k < KC; k++) mybin[k] = 0;

        const long base4 = (long)bid * PV;
        const int4*   lv = (const int4*)lbl     + base4;
        const float4* tv = (const float4*)tmask + base4;
        const float4* xv = (const float4*)masks + base4;
        uchar4*       sv = (uchar4*)g_seg + base4;

        float bce = 0.f;
#pragma unroll
        for (int it = 0; it < PIT; it++) {
            const int i = tid + it * T_;
            int4   L  = __ldcs(&lv[i]);
            float4 Tt = __ldcs(&tv[i]);
            float4 X  = __ldcs(&xv[i]);
            uchar4 s;
#define PREP1(comp)                                                            \
            {                                                                  \
                bool m = (Tt.comp != 0.f) && ((unsigned)L.comp < 32u);         \
                s.comp = m ? (unsigned char)L.comp : (unsigned char)255;       \
                if (m) mybin[L.comp] = mybin[L.comp] + 1;                      \
                float a = fabsf(X.comp);                                       \
                bce += fmaxf(X.comp, 0.f) - X.comp * Tt.comp                   \
                     + __logf(1.f + __expf(-a));                               \
            }
            PREP1(x) PREP1(y) PREP1(z) PREP1(w)
#undef PREP1
            sv[i] = s;
        }
        __syncthreads();

        float acc = 0.f;
#pragma unroll 8
        for (int t = 0; t < 32; t++) acc += (float)cnt8[(w * 32 + t) * 33 + lane];
        redC[w * 32 + lane] = acc;

        float bb = bce;
#pragma unroll
        for (int o = 16; o; o >>= 1) bb += __shfl_xor_sync(0xffffffffu, bb, o);
        if (lane == 0) redB[w] = bb;
        __syncthreads();

        if (w == 0) {
            float tot = redC[lane] + redC[32 + lane] + redC[64 + lane];
            g_pCnt[bid * KC + lane] = tot;
            if (lane == 0) g_pBce[bid] = redB[0] + redB[1] + redB[2];
        }
    }

    grid_sync();

    // ======================= P2: bins =======================
    {
        float2* bins = (float2*)sraw;   // 32*96 float2 = 24576 B
        const int be  = bid & 63;       // b*16 + e
        const int chv = bid >> 6;       // 0..11
        const int b   = be >> 4;

#pragma unroll
        for (int k = 0; k < KC; k++) bins[k * T_ + tid] = make_float2(0.f, 0.f);
        // per-thread-private columns: no block sync needed before accumulation

        const float4* evp = (const float4*)emb   + (long)be * N4_ + (long)chv * C4A + tid;
        const uchar4* svp = (const uchar4*)g_seg + (long)b  * N4_ + (long)chv * C4A + tid;

        float4 vb[4];
        uchar4 sb[4];
#pragma unroll
        for (int p = 0; p < 4; p++) {
            vb[p] = __ldcs(&evp[p * T_]);
            sb[p] = svp[p * T_];
        }

#pragma unroll 4
        for (int it = 0; it < BIT; it++) {
            float4 v = vb[it & 3];
            uchar4 s = sb[it & 3];
            if (it + 4 < BIT) {
                vb[it & 3] = __ldcs(&evp[(it + 4) * T_]);
                sb[it & 3] = svp[(it + 4) * T_];
            }
#define ACC1(sc, vc)                                                   \
            if (s.sc != 255) {                                         \
                float2 a = bins[(int)s.sc * T_ + tid];                 \
                a.x += v.vc; a.y += v.vc * v.vc;                       \
                bins[(int)s.sc * T_ + tid] = a;                        \
            }
            ACC1(x, x) ACC1(y, y) ACC1(z, z) ACC1(w, w)
#undef ACC1
        }
        __syncthreads();

        // warp w sums row k=lane over its 32-column window, +lane swizzled
        float2 acc = make_float2(0.f, 0.f);
#pragma unroll 8
        for (int t = 0; t < 32; t++) {
            int col = w * 32 + t + lane;
            if (col >= T_) col -= T_;
            float2 x = bins[lane * T_ + col];
            acc.x += x.x; acc.y += x.y;
        }
        __syncthreads();               // reads done -> reuse bins row 0
        bins[w * 32 + lane] = acc;
        __syncthreads();

        if (w == 0) {
            float2 t0 = bins[lane], t1 = bins[32 + lane], t2 = bins[64 + lane];
            float2 tot = make_float2(t0.x + t1.x + t2.x, t0.y + t1.y + t2.y);
            g_pSum[(be * CHA + chv) * KC + lane] = tot;
        }
    }

    grid_sync();

    // ======================= P3: partial reductions =======================
    {
        float2* red2 = (float2*)sraw;
        float*  redf = (float*)sraw;
        if (bid < 64) {
            float2 acc = make_float2(0.f, 0.f);
            for (int c = w; c < CHA; c += 3) {
                float2 x = g_pSum[(bid * CHA + c) * KC + lane];
                acc.x += x.x; acc.y += x.y;
            }
            red2[w * 32 + lane] = acc;
            __syncthreads();
            if (w == 0) {
                float2 a0 = red2[lane], a1 = red2[32 + lane], a2 = red2[64 + lane];
                g_sSum[bid * KC + lane] =
                    make_float2(a0.x + a1.x + a2.x, a0.y + a1.y + a2.y);
            }
        } else if (bid < 68) {
            const int b2 = bid - 64;
            float c = 0.f;
            for (int c0 = w; c0 < PB; c0 += 3)
                c += g_pCnt[(b2 * PB + c0) * KC + lane];
            redf[w * 32 + lane] = c;
            __syncthreads();
            if (w == 0)
                g_sCnt[b2 * KC + lane] = redf[lane] + redf[32 + lane] + redf[64 + lane];
        } else if (bid == 68) {
            float a = 0.f;
            for (int q = tid; q < GRID; q += T_) a += g_pBce[q];
#pragma unroll
            for (int o = 16; o; o >>= 1) a += __shfl_xor_sync(0xffffffffu, a, o);
            if (lane == 0) redf[w] = a;
            __syncthreads();
            if (tid == 0) g_sBce = redf[0] + redf[1] + redf[2];
        }
    }

    grid_sync();

    // ======================= P4: finalize (block 0) =======================
    if (bid == 0) {
        float (*sCent)[KC][E_ + 1] = (float (*)[KC][E_ + 1])sraw;   // 8704 B
        float* sRes = (float*)(sraw + B_ * KC * (E_ + 1) * 4);      // 12 floats

        for (int bb = w; bb < B_; bb += 3) {       // w0: b=0,3  w1: b=1  w2: b=2
            float cnt  = g_sCnt[bb * KC + lane];
            float safe = fmaxf(cnt, 1.f);
            float center[E_];
            float sq = 0.f, cs = 0.f;
#pragma unroll
            for (int e = 0; e < E_; e++) {
                float2 s = g_sSum[(bb * E_ + e) * KC + lane];
                float c = s.x / safe;
                center[e] = c;
                cs += c * c;
                sq += s.y;
                sCent[bb][lane][e] = c;
            }
            bool fg = (cnt > 0.f) && (lane > 0);
            unsigned fgm = __ballot_sync(0xffffffffu, fg);
            float C = (float)__popc(fgm);
            __syncwarp();

            float vi = fg ? (sq / safe - cs) : 0.f;
            float vr = fg ? sqrtf(cs) : 0.f;
            float hs = 0.f;
            for (int j = 0; j < KC; j++) {
                if ((fgm >> j) & 1u) {
                    float d2 = 0.f;
#pragma unroll
                    for (int e = 0; e < E_; e++) {
                        float d = center[e] - sCent[bb][j][e];
                        d2 += d * d;
                    }
                    if (fg && j != lane) {
                        float d = sqrtf(d2);
                        float h = fmaxf(2.f * 1.5f - d, 0.f);
                        hs += h * h;
                    }
                }
            }
#pragma unroll
            for (int o = 16; o; o >>= 1) {
                vi += __shfl_xor_sync(0xffffffffu, vi, o);
                vr += __shfl_xor_sync(0xffffffffu, vr, o);
                hs += __shfl_xor_sync(0xffffffffu, hs, o);
            }
            if (lane == 0) {
                float Cs = fmaxf(C, 1.f);
                sRes[bb * 3 + 0] = (C >= 1.f) ? vi / Cs : 0.f;
                sRes[bb * 3 + 1] = (C >= 2.f) ? hs / fmaxf(C * (C - 1.f), 1.f) : 0.f;
                sRes[bb * 3 + 2] = (C >= 1.f) ? vr / Cs : 0.f;
            }
        }
        __syncthreads();

        if (tid == 0) {
            float mi = 0.f, me = 0.f, mr = 0.f;
#pragma unroll
            for (int q = 0; q < B_; q++) {
                mi += sRes[q * 3 + 0]; me += sRes[q * 3 + 1]; mr += sRes[q * 3 + 2];
            }
            mi *= 0.25f; me *= 0.25f; mr *= 0.25f;
            float bce = g_sBce / (float)((long)B_ * N_);
            out[0] = 1.0f * mi + 1.0f * me + 0.001f + mr + bce;
        }
    }
}

// ---------------------------------------------------------------------------
extern "C" void kernel_launch(void* const* d_in, const int* in_sizes, int n_in,
                              void* d_out, int out_size)
{
    (void)in_sizes; (void)n_in; (void)out_size;
    const float* emb   = (const float*)d_in[0];  // [4,16,96^3] f32
    const float* masks = (const float*)d_in[1];  // [4,1,96^3]  f32 logits
    const int*   lbl   = (const int*)d_in[2];    // [4,1,96^3]  int32 labels
    const float* tmask = (const float*)d_in[3];  // [4,1,96^3]  f32 0/1
    float* out = (float*)d_out;

    k_all<<<GRID, T_>>>(emb, masks, lbl, tmask, out);
}

// round 9
// speedup vs baseline: 1.2903x; 1.0444x over previous
#include <cuda_runtime.h>
#include <cstdint>

// ---------------------------------------------------------------------------
// EmbeddingLoss, single persistent kernel with software grid barriers.
//   P1: prep  (seg u8, per-block counts, bce partials)
//   P2: bins  (segmented sum/sumsq, thread-private smem bins, ring prefetch)
//   P3: distributed partial reduction
//   P4: block 0 finalize -> scalar
// Templated on grid size; launcher picks 1152 (8 blocks/SM) when resident-
// safe, else falls back to 768. Barriers are integer-atomic; FP fixed-order.
// ---------------------------------------------------------------------------

constexpr int B_   = 4;
constexpr int E_   = 16;
constexpr int N_   = 96 * 96 * 96;   // 884736 voxels per batch
constexpr int N4_  = N_ / 4;         // 221184 float4 groups per batch
constexpr int KC   = 32;
constexpr int T_   = 96;             // threads per block (3 warps)

constexpr int CHA_MAX = 18;

__device__ unsigned char g_seg[(long)B_ * N_];        // 3.5 MB
__device__ float2        g_pSum[64 * CHA_MAX * KC];   // [be][ch][k]
__device__ float         g_pCnt[1152 * KC];           // [prep-block][k]
__device__ float         g_pBce[1152];
__device__ float2        g_sSum[64 * KC];
__device__ float         g_sCnt[B_ * KC];
__device__ float         g_sBce;

__device__ int          g_barc = 0;
__device__ volatile int g_barg = 0;

template<int GRIDN>
__device__ __forceinline__ void grid_sync()
{
    __syncthreads();
    if (threadIdx.x == 0) {
        __threadfence();
        int gen = g_barg;
        if (atomicAdd(&g_barc, 1) == GRIDN - 1) {
            g_barc = 0;
            __threadfence();
            g_barg = gen + 1;
        } else {
            while (g_barg == gen) { __nanosleep(64); }
            __threadfence();
        }
    }
    __syncthreads();
}

template<int GRIDN>
__global__ __launch_bounds__(T_, 8) void k_all(const float* __restrict__ emb,
                                               const float* __restrict__ masks,
                                               const int*   __restrict__ lbl,
                                               const float* __restrict__ tmask,
                                               float*       __restrict__ out)
{
    constexpr int PV  = (B_ * N4_) / GRIDN;  // float4 per prep slice
    constexpr int PIT = PV / T_;
    constexpr int PB  = GRIDN / B_;          // prep blocks per batch
    constexpr int CHA = GRIDN / 64;          // bins chunks per (b,e)
    constexpr int C4A = N4_ / CHA;
    constexpr int BIT = C4A / T_;
    static_assert(PV * T_ * 0 == 0 && PIT * T_ == PV && CHA * 64 == GRIDN
                  && C4A * CHA == N4_ && BIT * T_ == C4A, "partition");

    __shared__ __align__(16) unsigned char sraw[25600];   // unioned per phase

    const int tid  = threadIdx.x;
    const int bid  = blockIdx.x;
    const int lane = tid & 31;
    const int w    = tid >> 5;     // 0..2

    // ======================= P1: prep =======================
    {
        unsigned char* cnt8 = sraw;                       // 96*33 = 3168 B
        float* redC = (float*)(sraw + 3168);              // 3*32 floats
        float* redB = (float*)(sraw + 3168 + 3 * 32 * 4); // 3 floats

        unsigned char* mybin = cnt8 + tid * 33;
#pragma unroll
        for (int k = 0; k < KC; k++) mybin[k] = 0;

        const long base4 = (long)bid * PV;
        const int4*   lv = (const int4*)lbl     + base4;
        const float4* tv = (const float4*)tmask + base4;
        const float4* xv = (const float4*)masks + base4;
        uchar4*       sv = (uchar4*)g_seg + base4;

        float bce = 0.f;
#pragma unroll
        for (int it = 0; it < PIT; it++) {
            const int i = tid + it * T_;
            int4   L  = __ldcs(&lv[i]);
            float4 Tt = __ldcs(&tv[i]);
            float4 X  = __ldcs(&xv[i]);
            uchar4 s;
#define PREP1(comp)                                                            \
            {                                                                  \
                bool m = (Tt.comp != 0.f) && ((unsigned)L.comp < 32u);         \
                s.comp = m ? (unsigned char)L.comp : (unsigned char)255;       \
                if (m) mybin[L.comp] = mybin[L.comp] + 1;                      \
                float a = fabsf(X.comp);                                       \
                bce += fmaxf(X.comp, 0.f) - X.comp * Tt.comp                   \
                     + __logf(1.f + __expf(-a));                               \
            }
            PREP1(x) PREP1(y) PREP1(z) PREP1(w)
#undef PREP1
            sv[i] = s;
        }
        __syncthreads();

        float acc = 0.f;
#pragma unroll 8
        for (int t = 0; t < 32; t++) acc += (float)cnt8[(w * 32 + t) * 33 + lane];
        redC[w * 32 + lane] = acc;

        float bb = bce;
#pragma unroll
        for (int o = 16; o; o >>= 1) bb += __shfl_xor_sync(0xffffffffu, bb, o);
        if (lane == 0) redB[w] = bb;
        __syncthreads();

        if (w == 0) {
            float tot = redC[lane] + redC[32 + lane] + redC[64 + lane];
            g_pCnt[bid * KC + lane] = tot;
            if (lane == 0) g_pBce[bid] = redB[0] + redB[1] + redB[2];
        }
    }

    grid_sync<GRIDN>();

    // ======================= P2: bins =======================
    {
        float2* bins = (float2*)sraw;   // 32*96 float2 = 24576 B
        const int be  = bid & 63;       // b*16 + e
        const int chv = bid >> 6;       // 0..CHA-1
        const int b   = be >> 4;

#pragma unroll
        for (int k = 0; k < KC; k++) bins[k * T_ + tid] = make_float2(0.f, 0.f);
        // per-thread-private columns: no block sync needed before accumulation

        const float4* evp = (const float4*)emb   + (long)be * N4_ + (long)chv * C4A + tid;
        const uchar4* svp = (const uchar4*)g_seg + (long)b  * N4_ + (long)chv * C4A + tid;

        float4 vb[4];
        uchar4 sb[4];
#pragma unroll
        for (int p = 0; p < 4; p++) {
            vb[p] = __ldcs(&evp[p * T_]);
            sb[p] = svp[p * T_];
        }

#pragma unroll 4
        for (int it = 0; it < BIT; it++) {
            float4 v = vb[it & 3];
            uchar4 s = sb[it & 3];
            if (it + 4 < BIT) {
                vb[it & 3] = __ldcs(&evp[(it + 4) * T_]);
                sb[it & 3] = svp[(it + 4) * T_];
            }
#define ACC1(sc, vc)                                                   \
            if (s.sc != 255) {                                         \
                float2 a = bins[(int)s.sc * T_ + tid];                 \
                a.x += v.vc; a.y += v.vc * v.vc;                       \
                bins[(int)s.sc * T_ + tid] = a;                        \
            }
            ACC1(x, x) ACC1(y, y) ACC1(z, z) ACC1(w, w)
#undef ACC1
        }
        __syncthreads();

        // warp w sums row k=lane over its 32-column window, +lane swizzled
        float2 acc = make_float2(0.f, 0.f);
#pragma unroll 8
        for (int t = 0; t < 32; t++) {
            int col = w * 32 + t + lane;
            if (col >= T_) col -= T_;
            float2 x = bins[lane * T_ + col];
            acc.x += x.x; acc.y += x.y;
        }
        __syncthreads();               // reads done -> reuse bins row 0
        bins[w * 32 + lane] = acc;
        __syncthreads();

        if (w == 0) {
            float2 t0 = bins[lane], t1 = bins[32 + lane], t2 = bins[64 + lane];
            float2 tot = make_float2(t0.x + t1.x + t2.x, t0.y + t1.y + t2.y);
            g_pSum[(be * CHA + chv) * KC + lane] = tot;
        }
    }

    grid_sync<GRIDN>();

    // ======================= P3: partial reductions =======================
    {
        float2* red2 = (float2*)sraw;
        float*  redf = (float*)sraw;
        if (bid < 64) {
            float2 acc = make_float2(0.f, 0.f);
            for (int c = w; c < CHA; c += 3) {
                float2 x = g_pSum[(bid * CHA + c) * KC + lane];
                acc.x += x.x; acc.y += x.y;
            }
            red2[w * 32 + lane] = acc;
            __syncthreads();
            if (w == 0) {
                float2 a0 = red2[lane], a1 = red2[32 + lane], a2 = red2[64 + lane];
                g_sSum[bid * KC + lane] =
                    make_float2(a0.x + a1.x + a2.x, a0.y + a1.y + a2.y);
            }
        } else if (bid < 68) {
            const int b2 = bid - 64;
            float c = 0.f;
            for (int c0 = w; c0 < PB; c0 += 3)
                c += g_pCnt[(b2 * PB + c0) * KC + lane];
            redf[w * 32 + lane] = c;
            __syncthreads();
            if (w == 0)
                g_sCnt[b2 * KC + lane] = redf[lane] + redf[32 + lane] + redf[64 + lane];
        } else if (bid == 68) {
            float a = 0.f;
            for (int q = tid; q < GRIDN; q += T_) a += g_pBce[q];
#pragma unroll
            for (int o = 16; o; o >>= 1) a += __shfl_xor_sync(0xffffffffu, a, o);
            if (lane == 0) redf[w] = a;
            __syncthreads();
            if (tid == 0) g_sBce = redf[0] + redf[1] + redf[2];
        }
    }

    grid_sync<GRIDN>();

    // ======================= P4: finalize (block 0) =======================
    if (bid == 0) {
        float (*sCent)[KC][E_ + 1] = (float (*)[KC][E_ + 1])sraw;   // 8704 B
        float* sRes = (float*)(sraw + B_ * KC * (E_ + 1) * 4);      // 12 floats

        for (int bb = w; bb < B_; bb += 3) {       // w0: b=0,3  w1: b=1  w2: b=2
            float cnt  = g_sCnt[bb * KC + lane];
            float safe = fmaxf(cnt, 1.f);
            float center[E_];
            float sq = 0.f, cs = 0.f;
#pragma unroll
            for (int e = 0; e < E_; e++) {
                float2 s = g_sSum[(bb * E_ + e) * KC + lane];
                float c = s.x / safe;
                center[e] = c;
                cs += c * c;
                sq += s.y;
                sCent[bb][lane][e] = c;
            }
            bool fg = (cnt > 0.f) && (lane > 0);
            unsigned fgm = __ballot_sync(0xffffffffu, fg);
            float C = (float)__popc(fgm);
            __syncwarp();

            float vi = fg ? (sq / safe - cs) : 0.f;
            float vr = fg ? sqrtf(cs) : 0.f;
            float hs = 0.f;
            for (int j = 0; j < KC; j++) {
                if ((fgm >> j) & 1u) {
                    float d2 = 0.f;
#pragma unroll
                    for (int e = 0; e < E_; e++) {
                        float d = center[e] - sCent[bb][j][e];
                        d2 += d * d;
                    }
                    if (fg && j != lane) {
                        float d = sqrtf(d2);
                        float h = fmaxf(2.f * 1.5f - d, 0.f);
                        hs += h * h;
                    }
                }
            }
#pragma unroll
            for (int o = 16; o; o >>= 1) {
                vi += __shfl_xor_sync(0xffffffffu, vi, o);
                vr += __shfl_xor_sync(0xffffffffu, vr, o);
                hs += __shfl_xor_sync(0xffffffffu, hs, o);
            }
            if (lane == 0) {
                float Cs = fmaxf(C, 1.f);
                sRes[bb * 3 + 0] = (C >= 1.f) ? vi / Cs : 0.f;
                sRes[bb * 3 + 1] = (C >= 2.f) ? hs / fmaxf(C * (C - 1.f), 1.f) : 0.f;
                sRes[bb * 3 + 2] = (C >= 1.f) ? vr / Cs : 0.f;
            }
        }
        __syncthreads();

        if (tid == 0) {
            float mi = 0.f, me = 0.f, mr = 0.f;
#pragma unroll
            for (int q = 0; q < B_; q++) {
                mi += sRes[q * 3 + 0]; me += sRes[q * 3 + 1]; mr += sRes[q * 3 + 2];
            }
            mi *= 0.25f; me *= 0.25f; mr *= 0.25f;
            float bce = g_sBce / (float)((long)B_ * N_);
            out[0] = 1.0f * mi + 1.0f * me + 0.001f + mr + bce;
        }
    }
}

// ---------------------------------------------------------------------------
extern "C" void kernel_launch(void* const* d_in, const int* in_sizes, int n_in,
                              void* d_out, int out_size)
{
    (void)in_sizes; (void)n_in; (void)out_size;
    const float* emb   = (const float*)d_in[0];  // [4,16,96^3] f32
    const float* masks = (const float*)d_in[1];  // [4,1,96^3]  f32 logits
    const int*   lbl   = (const int*)d_in[2];    // [4,1,96^3]  int32 labels
    const float* tmask = (const float*)d_in[3];  // [4,1,96^3]  f32 0/1
    float* out = (float*)d_out;

    // Persistent grid MUST be fully resident (software grid barrier).
    // Pure host-side queries (capture-legal, deterministic) pick the grid.
    cudaFuncSetAttribute(k_all<1152>,
                         cudaFuncAttributePreferredSharedMemoryCarveout,
                         cudaSharedmemCarveoutMaxShared);
    cudaFuncSetAttribute(k_all<768>,
                         cudaFuncAttributePreferredSharedMemoryCarveout,
                         cudaSharedmemCarveoutMaxShared);
    int dev = 0;
    cudaGetDevice(&dev);
    int sms = 0;
    cudaDeviceGetAttribute(&sms, cudaDevAttrMultiProcessorCount, dev);
    int nb = 0;
    cudaOccupancyMaxActiveBlocksPerMultiprocessor(&nb, k_all<1152>, T_, 0);

    if ((long)nb * sms >= 1152)
        k_all<1152><<<1152, T_>>>(emb, masks, lbl, tmask, out);
    else
        k_all<768><<<768, T_>>>(emb, masks, lbl, tmask, out);
}